// round 15
// baseline (speedup 1.0000x reference)
#include <cuda_runtime.h>
#include <cuda_fp16.h>
#include <cstdint>
#include <cstddef>

#define BB 32
#define TT 512
#define DIN 256
#define HH 1024
#define G3 3072
#define DOUT 256
#define MTOT (BB*TT)
#define NCTA 128

// ---- static device scratch ----
__device__ float    g_gx[(size_t)MTOT*G3];
__device__ float    g_ha[BB*HH];
__device__ uint8_t  g_pHi[2][BB*HH*2];          // h hi halves, A-fragment order
__device__ uint8_t  g_AhF[(size_t)MTOT*HH*2];   // A fragments (hi)
__device__ uint8_t  g_BhF[(size_t)G3*HH*2];     // W fragments (hi)
__device__ uint8_t  g_BlF[(size_t)G3*HH*2];     // W fragments (lo)
__device__ unsigned g_bar;

// ---- helpers ----
__device__ __forceinline__ void mma16816(float* c, const uint32_t* a, const uint32_t* b){
    asm volatile("mma.sync.aligned.m16n8k16.row.col.f32.f16.f16.f32 "
        "{%0,%1,%2,%3}, {%4,%5,%6,%7}, {%8,%9}, {%0,%1,%2,%3};"
        : "+f"(c[0]),"+f"(c[1]),"+f"(c[2]),"+f"(c[3])
        : "r"(a[0]),"r"(a[1]),"r"(a[2]),"r"(a[3]),"r"(b[0]),"r"(b[1]));
}
__device__ __forceinline__ void split_h(float x, __half& hi, __half& lo){
    hi = __float2half_rn(x);
    lo = __float2half_rn(x - __half2float(hi));
}
__device__ __forceinline__ uint32_t pack_h2(__half a, __half b){
    __half2 v = __halves2half2(a, b);
    return *(uint32_t*)&v;
}
__device__ __forceinline__ void split2(float2 v, uint32_t& hi, uint32_t& lo){
    __half h0,l0,h1,l1;
    split_h(v.x,h0,l0); split_h(v.y,h1,l1);
    hi = pack_h2(h0,h1); lo = pack_h2(l0,l1);
}
__device__ __forceinline__ uint32_t cvt2_hi(float2 v){
    return pack_h2(__float2half_rn(v.x), __float2half_rn(v.y));
}
__device__ __forceinline__ void st_u16_cg(uint8_t* p, unsigned short v){
    asm volatile("st.global.cg.u16 [%0], %1;" :: "l"(p), "h"(v) : "memory");
}
__device__ __forceinline__ void st_u64_cg(uint8_t* p, uint2 v){
    asm volatile("st.global.cg.v2.u32 [%0], {%1,%2};" :: "l"(p), "r"(v.x), "r"(v.y) : "memory");
}
__device__ __forceinline__ uint4 ld_u128_cg(const uint8_t* p){
    uint4 v;
    asm volatile("ld.global.cg.v4.u32 {%0,%1,%2,%3}, [%4];"
                 : "=r"(v.x),"=r"(v.y),"=r"(v.z),"=r"(v.w) : "l"(p));
    return v;
}
__device__ __forceinline__ unsigned atom_add_release(unsigned* p, unsigned v){
    unsigned old;
    asm volatile("atom.add.release.gpu.u32 %0, [%1], %2;"
                 : "=r"(old) : "l"(p), "r"(v) : "memory");
    return old;
}
__device__ __forceinline__ unsigned ld_acquire_gpu(const unsigned* p){
    unsigned v;
    asm volatile("ld.acquire.gpu.u32 %0, [%1];" : "=r"(v) : "l"(p) : "memory");
    return v;
}

// ---------------------------------------------------------------------------
// Split fp32 matrix into mma A-fragment order, HI halves only.
// ---------------------------------------------------------------------------
__global__ __launch_bounds__(256) void splitA_frag(
    const float* __restrict__ X, uint8_t* __restrict__ Fh, int M, int K)
{
    int idx = blockIdx.x*256 + threadIdx.x;
    int KT = K >> 4;
    int total = (M >> 4) * KT * 32;
    if(idx >= total) return;
    int lane = idx & 31, tile = idx >> 5;
    int tk = tile % KT, tm = tile / KT;
    int grp = lane >> 2, tig = lane & 3;
    const float* p0 = X + (size_t)(tm*16+grp)*K + tk*16 + tig*2;
    const float* p1 = p0 + (size_t)8*K;
    uint4 hi;
    hi.x = cvt2_hi(*(const float2*)p0);
    hi.y = cvt2_hi(*(const float2*)p1);
    hi.z = cvt2_hi(*(const float2*)(p0+8));
    hi.w = cvt2_hi(*(const float2*)(p1+8));
    *(uint4*)(Fh + (size_t)idx*16) = hi;
}

// B-fragment order (hi + lo)
__global__ __launch_bounds__(256) void splitB_frag(
    const float* __restrict__ W, uint8_t* __restrict__ Fh,
    uint8_t* __restrict__ Fl, int N, int K)
{
    int idx = blockIdx.x*256 + threadIdx.x;
    int KT = K >> 4;
    int total = (N >> 3) * KT * 32;
    if(idx >= total) return;
    int lane = idx & 31, tile = idx >> 5;
    int tk = tile % KT, tn = tile / KT;
    int grp = lane >> 2, tig = lane & 3;
    const float* p = W + (size_t)(tn*8+grp)*K + tk*16 + tig*2;
    float2 v0 = *(const float2*)p;
    float2 v1 = *(const float2*)(p+8);
    uint2 hi, lo;
    split2(v0, hi.x, lo.x); split2(v1, hi.y, lo.y);
    *(uint2*)(Fh + (size_t)idx*8) = hi;
    *(uint2*)(Fl + (size_t)idx*8) = lo;
}

// ---------------------------------------------------------------------------
// Fragment-resident HMMA GEMM, 2-term (Ah*Bh + Ah*Bl). Zero smem.
// ---------------------------------------------------------------------------
__global__ __launch_bounds__(256) void gemm_hmma_frag(
    const uint8_t* __restrict__ AhF,
    const uint8_t* __restrict__ BhF, const uint8_t* __restrict__ BlF,
    const float* __restrict__ bias, float* __restrict__ C, int M, int N, int K)
{
    const int tid=threadIdx.x, warp=tid>>5, lane=tid&31;
    const int grp=lane>>2, tig=lane&3;
    const int warpM=warp>>2, warpN=warp&3;
    const int m0=blockIdx.y*128, n0=blockIdx.x*128;
    const int KT=K>>4;

    const uint4* aBase[4];
    const uint2* bhBase[4];
    const uint2* blBase[4];
#pragma unroll
    for(int mt=0;mt<4;mt++)
        aBase[mt] = (const uint4*)(AhF + ((size_t)((m0>>4)+warpM*4+mt)*KT*32 + lane)*16);
#pragma unroll
    for(int nt=0;nt<4;nt++){
        size_t o = ((size_t)((n0>>3)+warpN*4+nt)*KT*32 + lane)*8;
        bhBase[nt] = (const uint2*)(BhF + o);
        blBase[nt] = (const uint2*)(BlF + o);
    }

    float acc[4][4][4];
#pragma unroll
    for(int mt=0;mt<4;mt++)
#pragma unroll
        for(int nt=0;nt<4;nt++)
#pragma unroll
            for(int i=0;i<4;i++) acc[mt][nt][i]=0.f;

    uint4 AH[2][4];
    uint2 BH[2][4], BL[2][4];

    auto load = [&](int tk, int buf){
#pragma unroll
        for(int mt=0;mt<4;mt++)
            AH[buf][mt] = __ldg(aBase[mt] + (size_t)tk*32);
#pragma unroll
        for(int nt=0;nt<4;nt++){
            BH[buf][nt] = __ldg(bhBase[nt] + (size_t)tk*32);
            BL[buf][nt] = __ldg(blBase[nt] + (size_t)tk*32);
        }
    };
    auto domma = [&](int buf){
#pragma unroll
        for(int mt=0;mt<4;mt++){
#pragma unroll
            for(int nt=0;nt<4;nt++){
                mma16816(acc[mt][nt], (const uint32_t*)&AH[buf][mt], (const uint32_t*)&BH[buf][nt]);
                mma16816(acc[mt][nt], (const uint32_t*)&AH[buf][mt], (const uint32_t*)&BL[buf][nt]);
            }
        }
    };

    load(0, 0);
    for(int tk=0; tk<KT; tk+=2){
        load(tk+1, 1);
        domma(0);
        if(tk+2 < KT) load(tk+2, 0);
        domma(1);
    }

#pragma unroll
    for(int mt=0;mt<4;mt++){
        int r=m0+warpM*64+mt*16+grp;
#pragma unroll
        for(int nt=0;nt<4;nt++){
            int c=n0+warpN*32+nt*8+tig*2;
            float b0=bias[c], b1=bias[c+1];
            float2 v0={acc[mt][nt][0]+b0, acc[mt][nt][1]+b1};
            float2 v1={acc[mt][nt][2]+b0, acc[mt][nt][3]+b1};
            *(float2*)&C[(size_t)r*N+c]=v0;
            *(float2*)&C[(size_t)(r+8)*N+c]=v1;
        }
    }
}

// ---------------------------------------------------------------------------
// HMMA GRU scan: 2-term, register h_old, hoisted A-frag loads, gx
// double-buffered, COALESCED h-state publish (smem repack -> 2 warps x
// STG.64), out-writes go DIRECTLY into A-fragment layout for layer-1 GEMM.
// ---------------------------------------------------------------------------
__global__ __launch_bounds__(512) void gru_scan_hmma(
    const float* __restrict__ gx, const float* __restrict__ w_hh,
    const float* __restrict__ b_hh, uint8_t* __restrict__ aout, int writeOut)
{
    __shared__ float red[16*768];
    __shared__ __align__(8) __half hbuf[256];

    const int tid=threadIdx.x, warp=tid>>5, lane=tid&31, j0=blockIdx.x*8;
    const unsigned nCta=gridDim.x;
    const int grp=lane>>2, tig=lane&3;
    const int gkt = blockIdx.x>>1;     // column tile (16 neurons)
    const int qhi = blockIdx.x&1;      // which 8-neuron half of the tile

    uint32_t Bh[3][4][2], Bl[3][4][2];
#pragma unroll
    for(int nt=0; nt<3; nt++){
        const float* wr = w_hh + (size_t)(nt*HH + j0 + grp)*HH;
#pragma unroll
        for(int kt=0; kt<4; kt++){
            int k0 = warp*64 + kt*16 + tig*2;
            float f0=wr[k0], f1=wr[k0+1], f2=wr[k0+8], f3=wr[k0+9];
            __half h0,l0,h1,l1,h2,l2,h3,l3;
            split_h(f0,h0,l0); split_h(f1,h1,l1); split_h(f2,h2,l2); split_h(f3,h3,l3);
            Bh[nt][kt][0]=pack_h2(h0,h1); Bh[nt][kt][1]=pack_h2(h2,h3);
            Bl[nt][kt][0]=pack_h2(l0,l1); Bl[nt][kt][1]=pack_h2(l2,l3);
        }
    }

    const int gb=tid>>3, gnr=tid&7;
    float br_=0.f,bz_=0.f,bn_=0.f;
    float hold=0.f;
    float xr=0.f,xz=0.f,xn=0.f;
    int hb_idx=0;
    if(tid<256){
        br_=b_hh[j0+gnr]; bz_=b_hh[HH+j0+gnr]; bn_=b_hh[2*HH+j0+gnr];
        // hbuf slot for the coalesced repack (see store mapping below)
        int mt=gb>>4, r=gb&15;
        int ln=(r&7)*4+((gnr>>1)&3), ql=r>>3;
        hb_idx = mt*128 + ln*4 + ql*2 + (gnr&1);
        size_t gbase=((size_t)gb*TT)*G3+(j0+gnr);
        xr=__ldg(&gx[gbase]); xz=__ldg(&gx[gbase+HH]); xn=__ldg(&gx[gbase+2*HH]);
    }

#pragma unroll 1
    for(int t=0; t<TT; t++){
        const uint8_t* pHiC=g_pHi[t&1];
        uint8_t* pHiN=g_pHi[(t+1)&1];

        // Deferred out-write for step t-1: directly into A-fragment layout
        // (matrix row m = gb*TT + (t-1), column j = j0+gnr, KT=64)
        if(writeOut && tid<256 && t>0){
            int tp=t-1;
            __half hv=__float2half_rn(hold);
            size_t tm=(size_t)gb*32 + (tp>>4);
            int lane_a=(tp&7)*4 + (gnr>>1);
            size_t ab=((tm*64 + gkt)*32 + lane_a)*16
                      + (size_t)qhi*8 + ((tp&8)>>3)*4 + (gnr&1)*2;
            st_u16_cg(aout + ab, *(unsigned short*)&hv);
        }

        // ---- A-frag loads: single flight ----
        uint4 Ah[2][4];
#pragma unroll
        for(int mt=0; mt<2; mt++)
#pragma unroll
            for(int kt=0; kt<4; kt++){
                int gkt2=warp*4+kt;
                size_t off=(((size_t)(gkt2*2+mt))<<9)+lane*16;
                Ah[mt][kt]=ld_u128_cg(pHiC+off);
            }

#pragma unroll
        for(int mt=0; mt<2; mt++){
            float C[3][4];
#pragma unroll
            for(int nt=0;nt<3;nt++)
#pragma unroll
                for(int i=0;i<4;i++) C[nt][i]=0.f;
#pragma unroll
            for(int nt=0; nt<3; nt++){
#pragma unroll
                for(int kt=0; kt<4; kt++){
                    mma16816(C[nt], (const uint32_t*)&Ah[mt][kt], Bh[nt][kt]);
                    mma16816(C[nt], (const uint32_t*)&Ah[mt][kt], Bl[nt][kt]);
                }
            }
#pragma unroll
            for(int nt=0; nt<3; nt++){
                float* rb=&red[warp*768 + (mt*3+nt)*128];
                int p0=grp*8+tig*2;
                rb[p0]=C[nt][0]; rb[p0+1]=C[nt][1];
                rb[p0+64]=C[nt][2]; rb[p0+65]=C[nt][3];
            }
        }
        __syncthreads();

        float xr2=0.f,xz2=0.f,xn2=0.f;
        if(tid<256){
            int mt=gb>>4, r=gb&15;
            float pr=0.f,pz=0.f,pn=0.f;
#pragma unroll
            for(int w=0; w<16; w++){
                int base=w*768 + mt*384 + r*8 + gnr;
                pr+=red[base];
                pz+=red[base+128];
                pn+=red[base+256];
            }
            float rr=1.f/(1.f+__expf(-(xr+pr+br_)));
            float zz=1.f/(1.f+__expf(-(xz+pz+bz_)));
            float nn=tanhf(xn+rr*(pn+bn_));
            float hnew=(1.f-zz)*nn+zz*hold;
            hold=hnew;
            hbuf[hb_idx]=__float2half_rn(hnew);
            if(t+1<TT){
                size_t gbase=((size_t)gb*TT+(t+1))*G3+(j0+gnr);
                xr2=__ldg(&gx[gbase]); xz2=__ldg(&gx[gbase+HH]); xn2=__ldg(&gx[gbase+2*HH]);
            }
        }
        __syncthreads();

        // ---- coalesced h-state publish: 2 warps x 32 STG.64 ----
        if(tid<64){
            int w=tid>>5, ln=tid&31;
            uint2 v=*(const uint2*)&hbuf[w*128+ln*4];
            st_u64_cg(pHiN + (((size_t)(gkt*2+w))<<9) + ln*16 + qhi*8, v);
        }
        __syncthreads();

        // ---- CG-pattern barrier ----
        if(tid==0){
            atom_add_release(&g_bar, 1u);
            unsigned target=nCta*(unsigned)(t+1);
            while(ld_acquire_gpu(&g_bar) < target){}
        }
        __syncthreads();

        xr=xr2; xz=xz2; xn=xn2;
    }

    if(tid<256){
        if(writeOut){
            int tp=TT-1;
            __half hv=__float2half_rn(hold);
            size_t tm=(size_t)gb*32 + (tp>>4);
            int lane_a=(tp&7)*4 + (gnr>>1);
            size_t ab=((tm*64 + gkt)*32 + lane_a)*16
                      + (size_t)qhi*8 + ((tp&8)>>3)*4 + (gnr&1)*2;
            st_u16_cg(aout + ab, *(unsigned short*)&hv);
        }
        g_ha[gb*HH+j0+gnr]=hold;
    }
}

// ---- FC ----
__global__ __launch_bounds__(256) void fc_kernel(
    const float* __restrict__ h, const float* __restrict__ w,
    const float* __restrict__ bias, float* __restrict__ outp)
{
    int gw=(int)((blockIdx.x*blockDim.x+threadIdx.x)>>5), lane=threadIdx.x&31;
    if(gw>=BB*DOUT) return;
    int m=gw>>8, o=gw&255;
    float acc=0.f;
#pragma unroll
    for(int i=0;i<8;i++){
        float4 hv=*(const float4*)&h[m*HH+i*128+lane*4];
        float4 wv=*(const float4*)&w[o*HH+i*128+lane*4];
        acc+=hv.x*wv.x+hv.y*wv.y+hv.z*wv.z+hv.w*wv.w;
    }
#pragma unroll
    for(int off=16;off>0;off>>=1) acc+=__shfl_xor_sync(0xffffffffu,acc,off);
    if(lane==0) outp[m*DOUT+o]=1.f/(1.f+__expf(-(acc+bias[o])));
}

extern "C" void kernel_launch(void* const* d_in, const int* in_sizes, int n_in,
                              void* d_out, int out_size)
{
    const float* input=(const float*)d_in[0];
    const float* w_ih0=(const float*)d_in[1];
    const float* w_hh0=(const float*)d_in[2];
    const float* b_ih0=(const float*)d_in[3];
    const float* b_hh0=(const float*)d_in[4];
    const float* w_ih1=(const float*)d_in[5];
    const float* w_hh1=(const float*)d_in[6];
    const float* b_ih1=(const float*)d_in[7];
    const float* b_hh1=(const float*)d_in[8];
    const float* fc_w=(const float*)d_in[9];
    const float* fc_b=(const float*)d_in[10];
    float* outp=(float*)d_out;

    float *gx,*ha; unsigned* bar; uint8_t *pHi,*AhF,*BhF,*BlF;
    cudaGetSymbolAddress((void**)&gx,g_gx);
    cudaGetSymbolAddress((void**)&ha,g_ha);
    cudaGetSymbolAddress((void**)&bar,g_bar);
    cudaGetSymbolAddress((void**)&pHi,g_pHi);
    cudaGetSymbolAddress((void**)&AhF,g_AhF);
    cudaGetSymbolAddress((void**)&BhF,g_BhF);
    cudaGetSymbolAddress((void**)&BlF,g_BlF);

    dim3 ggrid(G3/128, MTOT/128);   // 24 x 128

    // ---- Layer 0 ----
    {
        int tA = (MTOT>>4)*(DIN>>4)*32;
        int tB = (G3>>3)*(DIN>>4)*32;
        splitA_frag<<<(tA+255)/256,256>>>(input, AhF, MTOT, DIN);
        splitB_frag<<<(tB+255)/256,256>>>(w_ih0, BhF, BlF, G3, DIN);
    }
    gemm_hmma_frag<<<ggrid,256>>>(AhF,BhF,BlF,b_ih0,gx,MTOT,G3,DIN);

    cudaMemsetAsync(pHi,0,BB*HH*2);            // h-frag buffer 0 = zeros
    cudaMemsetAsync(bar,0,sizeof(unsigned));
    // scan0 writes out0 DIRECTLY into A-fragment layout (overwrites layer-0
    // input frags in AhF, which gemm0 has already consumed)
    gru_scan_hmma<<<NCTA,512>>>(gx,w_hh0,b_hh0,AhF,1);
    cudaMemcpyAsync(outp+BB*DOUT,ha,BB*HH*sizeof(float),cudaMemcpyDeviceToDevice);

    // ---- Layer 1 (no splitA needed — AhF already in fragment form) ----
    {
        int tB = (G3>>3)*(HH>>4)*32;
        splitB_frag<<<(tB+255)/256,256>>>(w_ih1, BhF, BlF, G3, HH);
    }
    gemm_hmma_frag<<<ggrid,256>>>(AhF,BhF,BlF,b_ih1,gx,MTOT,G3,HH);

    cudaMemsetAsync(pHi,0,BB*HH*2);
    cudaMemsetAsync(bar,0,sizeof(unsigned));
    gru_scan_hmma<<<NCTA,512>>>(gx,w_hh1,b_hh1,nullptr,0);
    cudaMemcpyAsync(outp+BB*DOUT+BB*HH,ha,BB*HH*sizeof(float),cudaMemcpyDeviceToDevice);

    fc_kernel<<<(BB*DOUT*32)/256,256>>>(ha,fc_w,fc_b,outp);
}

// round 16
// speedup vs baseline: 1.0081x; 1.0081x over previous
#include <cuda_runtime.h>
#include <cuda_fp16.h>
#include <cstdint>
#include <cstddef>

#define BB 32
#define TT 512
#define DIN 256
#define HH 1024
#define G3 3072
#define DOUT 256
#define MTOT (BB*TT)
#define NCTA 128

// ---- static device scratch ----
__device__ float    g_gx[(size_t)MTOT*G3];
__device__ float    g_ha[BB*HH];
__device__ uint8_t  g_pHi[2][BB*HH*2];          // h hi halves, A-fragment order
__device__ uint8_t  g_AhF[(size_t)MTOT*HH*2];   // A fragments (hi)
__device__ uint8_t  g_BhF[(size_t)G3*HH*2];     // W fragments (hi)
__device__ uint8_t  g_BlF[(size_t)G3*HH*2];     // W fragments (lo)
__device__ unsigned g_bar;

// ---- helpers ----
__device__ __forceinline__ void mma16816(float* c, const uint32_t* a, const uint32_t* b){
    asm volatile("mma.sync.aligned.m16n8k16.row.col.f32.f16.f16.f32 "
        "{%0,%1,%2,%3}, {%4,%5,%6,%7}, {%8,%9}, {%0,%1,%2,%3};"
        : "+f"(c[0]),"+f"(c[1]),"+f"(c[2]),"+f"(c[3])
        : "r"(a[0]),"r"(a[1]),"r"(a[2]),"r"(a[3]),"r"(b[0]),"r"(b[1]));
}
__device__ __forceinline__ void split_h(float x, __half& hi, __half& lo){
    hi = __float2half_rn(x);
    lo = __float2half_rn(x - __half2float(hi));
}
__device__ __forceinline__ uint32_t pack_h2(__half a, __half b){
    __half2 v = __halves2half2(a, b);
    return *(uint32_t*)&v;
}
__device__ __forceinline__ void split2(float2 v, uint32_t& hi, uint32_t& lo){
    __half h0,l0,h1,l1;
    split_h(v.x,h0,l0); split_h(v.y,h1,l1);
    hi = pack_h2(h0,h1); lo = pack_h2(l0,l1);
}
__device__ __forceinline__ uint32_t cvt2_hi(float2 v){
    return pack_h2(__float2half_rn(v.x), __float2half_rn(v.y));
}
__device__ __forceinline__ void st_u16_cg(uint8_t* p, unsigned short v){
    asm volatile("st.global.cg.u16 [%0], %1;" :: "l"(p), "h"(v) : "memory");
}
__device__ __forceinline__ uint4 ld_u128_cg(const uint8_t* p){
    uint4 v;
    asm volatile("ld.global.cg.v4.u32 {%0,%1,%2,%3}, [%4];"
                 : "=r"(v.x),"=r"(v.y),"=r"(v.z),"=r"(v.w) : "l"(p));
    return v;
}
__device__ __forceinline__ unsigned atom_add_release(unsigned* p, unsigned v){
    unsigned old;
    asm volatile("atom.add.release.gpu.u32 %0, [%1], %2;"
                 : "=r"(old) : "l"(p), "r"(v) : "memory");
    return old;
}
__device__ __forceinline__ unsigned ld_acquire_gpu(const unsigned* p){
    unsigned v;
    asm volatile("ld.acquire.gpu.u32 %0, [%1];" : "=r"(v) : "l"(p) : "memory");
    return v;
}

// ---------------------------------------------------------------------------
// Split fp32 matrix into mma A-fragment order, HI halves only.
// ---------------------------------------------------------------------------
__global__ __launch_bounds__(256) void splitA_frag(
    const float* __restrict__ X, uint8_t* __restrict__ Fh, int M, int K)
{
    int idx = blockIdx.x*256 + threadIdx.x;
    int KT = K >> 4;
    int total = (M >> 4) * KT * 32;
    if(idx >= total) return;
    int lane = idx & 31, tile = idx >> 5;
    int tk = tile % KT, tm = tile / KT;
    int grp = lane >> 2, tig = lane & 3;
    const float* p0 = X + (size_t)(tm*16+grp)*K + tk*16 + tig*2;
    const float* p1 = p0 + (size_t)8*K;
    uint4 hi;
    hi.x = cvt2_hi(*(const float2*)p0);
    hi.y = cvt2_hi(*(const float2*)p1);
    hi.z = cvt2_hi(*(const float2*)(p0+8));
    hi.w = cvt2_hi(*(const float2*)(p1+8));
    *(uint4*)(Fh + (size_t)idx*16) = hi;
}

// B-fragment order (hi + lo)
__global__ __launch_bounds__(256) void splitB_frag(
    const float* __restrict__ W, uint8_t* __restrict__ Fh,
    uint8_t* __restrict__ Fl, int N, int K)
{
    int idx = blockIdx.x*256 + threadIdx.x;
    int KT = K >> 4;
    int total = (N >> 3) * KT * 32;
    if(idx >= total) return;
    int lane = idx & 31, tile = idx >> 5;
    int tk = tile % KT, tn = tile / KT;
    int grp = lane >> 2, tig = lane & 3;
    const float* p = W + (size_t)(tn*8+grp)*K + tk*16 + tig*2;
    float2 v0 = *(const float2*)p;
    float2 v1 = *(const float2*)(p+8);
    uint2 hi, lo;
    split2(v0, hi.x, lo.x); split2(v1, hi.y, lo.y);
    *(uint2*)(Fh + (size_t)idx*8) = hi;
    *(uint2*)(Fl + (size_t)idx*8) = lo;
}

// ---------------------------------------------------------------------------
// Fragment-resident HMMA GEMM, 2-term (Ah*Bh + Ah*Bl). Zero smem.
// ---------------------------------------------------------------------------
__global__ __launch_bounds__(256) void gemm_hmma_frag(
    const uint8_t* __restrict__ AhF,
    const uint8_t* __restrict__ BhF, const uint8_t* __restrict__ BlF,
    const float* __restrict__ bias, float* __restrict__ C, int M, int N, int K)
{
    const int tid=threadIdx.x, warp=tid>>5, lane=tid&31;
    const int grp=lane>>2, tig=lane&3;
    const int warpM=warp>>2, warpN=warp&3;
    const int m0=blockIdx.y*128, n0=blockIdx.x*128;
    const int KT=K>>4;

    const uint4* aBase[4];
    const uint2* bhBase[4];
    const uint2* blBase[4];
#pragma unroll
    for(int mt=0;mt<4;mt++)
        aBase[mt] = (const uint4*)(AhF + ((size_t)((m0>>4)+warpM*4+mt)*KT*32 + lane)*16);
#pragma unroll
    for(int nt=0;nt<4;nt++){
        size_t o = ((size_t)((n0>>3)+warpN*4+nt)*KT*32 + lane)*8;
        bhBase[nt] = (const uint2*)(BhF + o);
        blBase[nt] = (const uint2*)(BlF + o);
    }

    float acc[4][4][4];
#pragma unroll
    for(int mt=0;mt<4;mt++)
#pragma unroll
        for(int nt=0;nt<4;nt++)
#pragma unroll
            for(int i=0;i<4;i++) acc[mt][nt][i]=0.f;

    uint4 AH[2][4];
    uint2 BH[2][4], BL[2][4];

    auto load = [&](int tk, int buf){
#pragma unroll
        for(int mt=0;mt<4;mt++)
            AH[buf][mt] = __ldg(aBase[mt] + (size_t)tk*32);
#pragma unroll
        for(int nt=0;nt<4;nt++){
            BH[buf][nt] = __ldg(bhBase[nt] + (size_t)tk*32);
            BL[buf][nt] = __ldg(blBase[nt] + (size_t)tk*32);
        }
    };
    auto domma = [&](int buf){
#pragma unroll
        for(int mt=0;mt<4;mt++){
#pragma unroll
            for(int nt=0;nt<4;nt++){
                mma16816(acc[mt][nt], (const uint32_t*)&AH[buf][mt], (const uint32_t*)&BH[buf][nt]);
                mma16816(acc[mt][nt], (const uint32_t*)&AH[buf][mt], (const uint32_t*)&BL[buf][nt]);
            }
        }
    };

    load(0, 0);
    for(int tk=0; tk<KT; tk+=2){
        load(tk+1, 1);
        domma(0);
        if(tk+2 < KT) load(tk+2, 0);
        domma(1);
    }

#pragma unroll
    for(int mt=0;mt<4;mt++){
        int r=m0+warpM*64+mt*16+grp;
#pragma unroll
        for(int nt=0;nt<4;nt++){
            int c=n0+warpN*32+nt*8+tig*2;
            float b0=bias[c], b1=bias[c+1];
            float2 v0={acc[mt][nt][0]+b0, acc[mt][nt][1]+b1};
            float2 v1={acc[mt][nt][2]+b0, acc[mt][nt][3]+b1};
            *(float2*)&C[(size_t)r*N+c]=v0;
            *(float2*)&C[(size_t)(r+8)*N+c]=v1;
        }
    }
}

// ---------------------------------------------------------------------------
// HMMA GRU scan (R14-proven body): 2-term, register h_old, hoisted A-frag
// loads, gx double-buffered, SCATTERED u16 h-publish, release-atomic barrier.
// Out-writes go DIRECTLY into A-fragment layout for layer-1 GEMM (R15-proven).
// ---------------------------------------------------------------------------
__global__ __launch_bounds__(512) void gru_scan_hmma(
    const float* __restrict__ gx, const float* __restrict__ w_hh,
    const float* __restrict__ b_hh, uint8_t* __restrict__ aout, int writeOut)
{
    __shared__ float red[16*768];

    const int tid=threadIdx.x, warp=tid>>5, lane=tid&31, j0=blockIdx.x*8;
    const unsigned nCta=gridDim.x;
    const int grp=lane>>2, tig=lane&3;
    const int gkt = blockIdx.x>>1;     // column tile (16 neurons)
    const int qhi = blockIdx.x&1;      // which 8-neuron half of the tile

    uint32_t Bh[3][4][2], Bl[3][4][2];
#pragma unroll
    for(int nt=0; nt<3; nt++){
        const float* wr = w_hh + (size_t)(nt*HH + j0 + grp)*HH;
#pragma unroll
        for(int kt=0; kt<4; kt++){
            int k0 = warp*64 + kt*16 + tig*2;
            float f0=wr[k0], f1=wr[k0+1], f2=wr[k0+8], f3=wr[k0+9];
            __half h0,l0,h1,l1,h2,l2,h3,l3;
            split_h(f0,h0,l0); split_h(f1,h1,l1); split_h(f2,h2,l2); split_h(f3,h3,l3);
            Bh[nt][kt][0]=pack_h2(h0,h1); Bh[nt][kt][1]=pack_h2(h2,h3);
            Bl[nt][kt][0]=pack_h2(l0,l1); Bl[nt][kt][1]=pack_h2(l2,l3);
        }
    }

    const int gb=tid>>3, gnr=tid&7;
    float br_=0.f,bz_=0.f,bn_=0.f;
    size_t woff=0;
    float hold=0.f;                       // h_old in a register (h0 = 0)
    float xr=0.f,xz=0.f,xn=0.f;           // gx for current step (prefetched)
    if(tid<256){
        br_=b_hh[j0+gnr]; bz_=b_hh[HH+j0+gnr]; bn_=b_hh[2*HH+j0+gnr];
        int j=j0+gnr, jkt=j>>4, c=j&15, mt=gb>>4, r=gb&15;
        int ln=(r&7)*4+((c>>1)&3), q=((r>>3)&1)+2*((c>>3)&1);
        woff=(((size_t)(jkt*2+mt))<<9) + ln*16 + q*4 + (c&1)*2;
        // preload gx for t=0
        size_t gbase=((size_t)gb*TT)*G3+(j0+gnr);
        xr=__ldg(&gx[gbase]); xz=__ldg(&gx[gbase+HH]); xn=__ldg(&gx[gbase+2*HH]);
    }

#pragma unroll 1
    for(int t=0; t<TT; t++){
        const uint8_t* pHiC=g_pHi[t&1];
        uint8_t* pHiN=g_pHi[(t+1)&1];

        // Deferred out-write for step t-1: directly into A-fragment layout
        // (matrix row m = gb*TT + (t-1), column j = j0+gnr, KT=64)
        if(writeOut && tid<256 && t>0){
            int tp=t-1;
            __half hv=__float2half_rn(hold);
            size_t tm=(size_t)gb*32 + (tp>>4);
            int lane_a=(tp&7)*4 + (gnr>>1);
            size_t ab=((tm*64 + gkt)*32 + lane_a)*16
                      + (size_t)qhi*8 + ((tp&8)>>3)*4 + (gnr&1)*2;
            st_u16_cg(aout + ab, *(unsigned short*)&hv);
        }

        // ---- A-frag loads: single flight ----
        uint4 Ah[2][4];
#pragma unroll
        for(int mt=0; mt<2; mt++)
#pragma unroll
            for(int kt=0; kt<4; kt++){
                int gkt2=warp*4+kt;
                size_t off=(((size_t)(gkt2*2+mt))<<9)+lane*16;
                Ah[mt][kt]=ld_u128_cg(pHiC+off);
            }

#pragma unroll
        for(int mt=0; mt<2; mt++){
            float C[3][4];
#pragma unroll
            for(int nt=0;nt<3;nt++)
#pragma unroll
                for(int i=0;i<4;i++) C[nt][i]=0.f;
#pragma unroll
            for(int nt=0; nt<3; nt++){
#pragma unroll
                for(int kt=0; kt<4; kt++){
                    mma16816(C[nt], (const uint32_t*)&Ah[mt][kt], Bh[nt][kt]);
                    mma16816(C[nt], (const uint32_t*)&Ah[mt][kt], Bl[nt][kt]);
                }
            }
#pragma unroll
            for(int nt=0; nt<3; nt++){
                float* rb=&red[warp*768 + (mt*3+nt)*128];
                int p0=grp*8+tig*2;
                rb[p0]=C[nt][0]; rb[p0+1]=C[nt][1];
                rb[p0+64]=C[nt][2]; rb[p0+65]=C[nt][3];
            }
        }
        __syncthreads();

        float xr2=0.f,xz2=0.f,xn2=0.f;
        if(tid<256){
            int mt=gb>>4, r=gb&15;
            float pr=0.f,pz=0.f,pn=0.f;
#pragma unroll
            for(int w=0; w<16; w++){
                int base=w*768 + mt*384 + r*8 + gnr;
                pr+=red[base];
                pz+=red[base+128];
                pn+=red[base+256];
            }
            float rr=1.f/(1.f+__expf(-(xr+pr+br_)));
            float zz=1.f/(1.f+__expf(-(xz+pz+bz_)));
            float nn=tanhf(xn+rr*(pn+bn_));
            float hnew=(1.f-zz)*nn+zz*hold;
            hold=hnew;
            __half hi=__float2half_rn(hnew);
            st_u16_cg(pHiN+woff, *(unsigned short*)&hi);
            // prefetch gx for t+1 (independent of h; in flight across barrier)
            if(t+1<TT){
                size_t gbase=((size_t)gb*TT+(t+1))*G3+(j0+gnr);
                xr2=__ldg(&gx[gbase]); xz2=__ldg(&gx[gbase+HH]); xn2=__ldg(&gx[gbase+2*HH]);
            }
        }

        // ---- CG-pattern barrier: sync -> release-arrive -> acquire-spin -> sync
        __syncthreads();
        if(tid==0){
            atom_add_release(&g_bar, 1u);
            unsigned target=nCta*(unsigned)(t+1);
            while(ld_acquire_gpu(&g_bar) < target){}
        }
        __syncthreads();

        xr=xr2; xz=xz2; xn=xn2;
    }

    if(tid<256){
        if(writeOut){
            int tp=TT-1;
            __half hv=__float2half_rn(hold);
            size_t tm=(size_t)gb*32 + (tp>>4);
            int lane_a=(tp&7)*4 + (gnr>>1);
            size_t ab=((tm*64 + gkt)*32 + lane_a)*16
                      + (size_t)qhi*8 + ((tp&8)>>3)*4 + (gnr&1)*2;
            st_u16_cg(aout + ab, *(unsigned short*)&hv);
        }
        g_ha[gb*HH+j0+gnr]=hold;
    }
}

// ---- FC ----
__global__ __launch_bounds__(256) void fc_kernel(
    const float* __restrict__ h, const float* __restrict__ w,
    const float* __restrict__ bias, float* __restrict__ outp)
{
    int gw=(int)((blockIdx.x*blockDim.x+threadIdx.x)>>5), lane=threadIdx.x&31;
    if(gw>=BB*DOUT) return;
    int m=gw>>8, o=gw&255;
    float acc=0.f;
#pragma unroll
    for(int i=0;i<8;i++){
        float4 hv=*(const float4*)&h[m*HH+i*128+lane*4];
        float4 wv=*(const float4*)&w[o*HH+i*128+lane*4];
        acc+=hv.x*wv.x+hv.y*wv.y+hv.z*wv.z+hv.w*wv.w;
    }
#pragma unroll
    for(int off=16;off>0;off>>=1) acc+=__shfl_xor_sync(0xffffffffu,acc,off);
    if(lane==0) outp[m*DOUT+o]=1.f/(1.f+__expf(-(acc+bias[o])));
}

extern "C" void kernel_launch(void* const* d_in, const int* in_sizes, int n_in,
                              void* d_out, int out_size)
{
    const float* input=(const float*)d_in[0];
    const float* w_ih0=(const float*)d_in[1];
    const float* w_hh0=(const float*)d_in[2];
    const float* b_ih0=(const float*)d_in[3];
    const float* b_hh0=(const float*)d_in[4];
    const float* w_ih1=(const float*)d_in[5];
    const float* w_hh1=(const float*)d_in[6];
    const float* b_ih1=(const float*)d_in[7];
    const float* b_hh1=(const float*)d_in[8];
    const float* fc_w=(const float*)d_in[9];
    const float* fc_b=(const float*)d_in[10];
    float* outp=(float*)d_out;

    float *gx,*ha; unsigned* bar; uint8_t *pHi,*AhF,*BhF,*BlF;
    cudaGetSymbolAddress((void**)&gx,g_gx);
    cudaGetSymbolAddress((void**)&ha,g_ha);
    cudaGetSymbolAddress((void**)&bar,g_bar);
    cudaGetSymbolAddress((void**)&pHi,g_pHi);
    cudaGetSymbolAddress((void**)&AhF,g_AhF);
    cudaGetSymbolAddress((void**)&BhF,g_BhF);
    cudaGetSymbolAddress((void**)&BlF,g_BlF);

    dim3 ggrid(G3/128, MTOT/128);   // 24 x 128

    // ---- Layer 0 ----
    {
        int tA = (MTOT>>4)*(DIN>>4)*32;
        int tB = (G3>>3)*(DIN>>4)*32;
        splitA_frag<<<(tA+255)/256,256>>>(input, AhF, MTOT, DIN);
        splitB_frag<<<(tB+255)/256,256>>>(w_ih0, BhF, BlF, G3, DIN);
    }
    gemm_hmma_frag<<<ggrid,256>>>(AhF,BhF,BlF,b_ih0,gx,MTOT,G3,DIN);

    cudaMemsetAsync(pHi,0,BB*HH*2);            // h-frag buffer 0 = zeros
    cudaMemsetAsync(bar,0,sizeof(unsigned));
    // scan0 writes out0 DIRECTLY into A-fragment layout (overwrites layer-0
    // input frags in AhF, already consumed by gemm0)
    gru_scan_hmma<<<NCTA,512>>>(gx,w_hh0,b_hh0,AhF,1);
    cudaMemcpyAsync(outp+BB*DOUT,ha,BB*HH*sizeof(float),cudaMemcpyDeviceToDevice);

    // ---- Layer 1 (no splitA needed — AhF already in fragment form) ----
    {
        int tB = (G3>>3)*(HH>>4)*32;
        splitB_frag<<<(tB+255)/256,256>>>(w_ih1, BhF, BlF, G3, HH);
    }
    gemm_hmma_frag<<<ggrid,256>>>(AhF,BhF,BlF,b_ih1,gx,MTOT,G3,HH);

    cudaMemsetAsync(pHi,0,BB*HH*2);
    cudaMemsetAsync(bar,0,sizeof(unsigned));
    gru_scan_hmma<<<NCTA,512>>>(gx,w_hh1,b_hh1,nullptr,0);
    cudaMemcpyAsync(outp+BB*DOUT+BB*HH,ha,BB*HH*sizeof(float),cudaMemcpyDeviceToDevice);

    fc_kernel<<<(BB*DOUT*32)/256,256>>>(ha,fc_w,fc_b,outp);
}

// round 17
// speedup vs baseline: 1.0403x; 1.0319x over previous
#include <cuda_runtime.h>
#include <cuda_fp16.h>
#include <cstdint>
#include <cstddef>

#define BB 32
#define TT 512
#define DIN 256
#define HH 1024
#define G3 3072
#define DOUT 256
#define MTOT (BB*TT)
#define NCTA 128

// ---- static device scratch ----
__device__ float    g_gx[(size_t)MTOT*G3];
__device__ float    g_ha[BB*HH];
__device__ uint8_t  g_pHi[2][BB*HH*2];          // h hi halves, A-fragment order
__device__ uint8_t  g_AhF[(size_t)MTOT*HH*2];   // A fragments (hi)
__device__ uint8_t  g_BhF[(size_t)G3*HH*2];     // W fragments (hi)
__device__ uint8_t  g_BlF[(size_t)G3*HH*2];     // W fragments (lo)
__device__ unsigned g_bar;

// ---- helpers ----
__device__ __forceinline__ void mma16816(float* c, const uint32_t* a, const uint32_t* b){
    asm volatile("mma.sync.aligned.m16n8k16.row.col.f32.f16.f16.f32 "
        "{%0,%1,%2,%3}, {%4,%5,%6,%7}, {%8,%9}, {%0,%1,%2,%3};"
        : "+f"(c[0]),"+f"(c[1]),"+f"(c[2]),"+f"(c[3])
        : "r"(a[0]),"r"(a[1]),"r"(a[2]),"r"(a[3]),"r"(b[0]),"r"(b[1]));
}
__device__ __forceinline__ void split_h(float x, __half& hi, __half& lo){
    hi = __float2half_rn(x);
    lo = __float2half_rn(x - __half2float(hi));
}
__device__ __forceinline__ uint32_t pack_h2(__half a, __half b){
    __half2 v = __halves2half2(a, b);
    return *(uint32_t*)&v;
}
__device__ __forceinline__ void split2(float2 v, uint32_t& hi, uint32_t& lo){
    __half h0,l0,h1,l1;
    split_h(v.x,h0,l0); split_h(v.y,h1,l1);
    hi = pack_h2(h0,h1); lo = pack_h2(l0,l1);
}
__device__ __forceinline__ uint32_t cvt2_hi(float2 v){
    return pack_h2(__float2half_rn(v.x), __float2half_rn(v.y));
}
__device__ __forceinline__ void st_u16_cg(uint8_t* p, unsigned short v){
    asm volatile("st.global.cg.u16 [%0], %1;" :: "l"(p), "h"(v) : "memory");
}
__device__ __forceinline__ uint4 ld_u128_cg(const uint8_t* p){
    uint4 v;
    asm volatile("ld.global.cg.v4.u32 {%0,%1,%2,%3}, [%4];"
                 : "=r"(v.x),"=r"(v.y),"=r"(v.z),"=r"(v.w) : "l"(p));
    return v;
}
__device__ __forceinline__ unsigned atom_add_release(unsigned* p, unsigned v){
    unsigned old;
    asm volatile("atom.add.release.gpu.u32 %0, [%1], %2;"
                 : "=r"(old) : "l"(p), "r"(v) : "memory");
    return old;
}
__device__ __forceinline__ unsigned ld_acquire_gpu(const unsigned* p){
    unsigned v;
    asm volatile("ld.acquire.gpu.u32 %0, [%1];" : "=r"(v) : "l"(p) : "memory");
    return v;
}

// ---------------------------------------------------------------------------
// Split fp32 matrix into mma A-fragment order, HI halves only.
// ---------------------------------------------------------------------------
__global__ __launch_bounds__(256) void splitA_frag(
    const float* __restrict__ X, uint8_t* __restrict__ Fh, int M, int K)
{
    int idx = blockIdx.x*256 + threadIdx.x;
    int KT = K >> 4;
    int total = (M >> 4) * KT * 32;
    if(idx >= total) return;
    int lane = idx & 31, tile = idx >> 5;
    int tk = tile % KT, tm = tile / KT;
    int grp = lane >> 2, tig = lane & 3;
    const float* p0 = X + (size_t)(tm*16+grp)*K + tk*16 + tig*2;
    const float* p1 = p0 + (size_t)8*K;
    uint4 hi;
    hi.x = cvt2_hi(*(const float2*)p0);
    hi.y = cvt2_hi(*(const float2*)p1);
    hi.z = cvt2_hi(*(const float2*)(p0+8));
    hi.w = cvt2_hi(*(const float2*)(p1+8));
    *(uint4*)(Fh + (size_t)idx*16) = hi;
}

// B-fragment order (hi + lo)
__global__ __launch_bounds__(256) void splitB_frag(
    const float* __restrict__ W, uint8_t* __restrict__ Fh,
    uint8_t* __restrict__ Fl, int N, int K)
{
    int idx = blockIdx.x*256 + threadIdx.x;
    int KT = K >> 4;
    int total = (N >> 3) * KT * 32;
    if(idx >= total) return;
    int lane = idx & 31, tile = idx >> 5;
    int tk = tile % KT, tn = tile / KT;
    int grp = lane >> 2, tig = lane & 3;
    const float* p = W + (size_t)(tn*8+grp)*K + tk*16 + tig*2;
    float2 v0 = *(const float2*)p;
    float2 v1 = *(const float2*)(p+8);
    uint2 hi, lo;
    split2(v0, hi.x, lo.x); split2(v1, hi.y, lo.y);
    *(uint2*)(Fh + (size_t)idx*8) = hi;
    *(uint2*)(Fl + (size_t)idx*8) = lo;
}

// ---------------------------------------------------------------------------
// Fragment-resident HMMA GEMM, 2-term (Ah*Bh + Ah*Bl). Zero smem.
// 4-buffer ring, depth-3 prefetch: hides L2 latency behind 3 domma blocks.
// ---------------------------------------------------------------------------
__global__ __launch_bounds__(256) void gemm_hmma_frag(
    const uint8_t* __restrict__ AhF,
    const uint8_t* __restrict__ BhF, const uint8_t* __restrict__ BlF,
    const float* __restrict__ bias, float* __restrict__ C, int M, int N, int K)
{
    const int tid=threadIdx.x, warp=tid>>5, lane=tid&31;
    const int grp=lane>>2, tig=lane&3;
    const int warpM=warp>>2, warpN=warp&3;
    const int m0=blockIdx.y*128, n0=blockIdx.x*128;
    const int KT=K>>4;

    const uint4* aBase[4];
    const uint2* bhBase[4];
    const uint2* blBase[4];
#pragma unroll
    for(int mt=0;mt<4;mt++)
        aBase[mt] = (const uint4*)(AhF + ((size_t)((m0>>4)+warpM*4+mt)*KT*32 + lane)*16);
#pragma unroll
    for(int nt=0;nt<4;nt++){
        size_t o = ((size_t)((n0>>3)+warpN*4+nt)*KT*32 + lane)*8;
        bhBase[nt] = (const uint2*)(BhF + o);
        blBase[nt] = (const uint2*)(BlF + o);
    }

    float acc[4][4][4];
#pragma unroll
    for(int mt=0;mt<4;mt++)
#pragma unroll
        for(int nt=0;nt<4;nt++)
#pragma unroll
            for(int i=0;i<4;i++) acc[mt][nt][i]=0.f;

    uint4 AH[4][4];
    uint2 BH[4][4], BL[4][4];

    auto load = [&](int tk, int buf){
#pragma unroll
        for(int mt=0;mt<4;mt++)
            AH[buf][mt] = __ldg(aBase[mt] + (size_t)tk*32);
#pragma unroll
        for(int nt=0;nt<4;nt++){
            BH[buf][nt] = __ldg(bhBase[nt] + (size_t)tk*32);
            BL[buf][nt] = __ldg(blBase[nt] + (size_t)tk*32);
        }
    };
    auto domma = [&](int buf){
#pragma unroll
        for(int mt=0;mt<4;mt++){
#pragma unroll
            for(int nt=0;nt<4;nt++){
                mma16816(acc[mt][nt], (const uint32_t*)&AH[buf][mt], (const uint32_t*)&BH[buf][nt]);
                mma16816(acc[mt][nt], (const uint32_t*)&AH[buf][mt], (const uint32_t*)&BL[buf][nt]);
            }
        }
    };

    // depth-3 prologue
    load(0,0); load(1,1); load(2,2);
    for(int tk=0; tk<KT; tk+=4){           // KT divisible by 4 (16 or 64)
        if(tk+3<KT) load(tk+3,3);
        domma(0);
        if(tk+4<KT) load(tk+4,0);
        domma(1);
        if(tk+5<KT) load(tk+5,1);
        domma(2);
        if(tk+6<KT) load(tk+6,2);
        domma(3);
    }

#pragma unroll
    for(int mt=0;mt<4;mt++){
        int r=m0+warpM*64+mt*16+grp;
#pragma unroll
        for(int nt=0;nt<4;nt++){
            int c=n0+warpN*32+nt*8+tig*2;
            float b0=bias[c], b1=bias[c+1];
            float2 v0={acc[mt][nt][0]+b0, acc[mt][nt][1]+b1};
            float2 v1={acc[mt][nt][2]+b0, acc[mt][nt][3]+b1};
            *(float2*)&C[(size_t)r*N+c]=v0;
            *(float2*)&C[(size_t)(r+8)*N+c]=v1;
        }
    }
}

// ---------------------------------------------------------------------------
// HMMA GRU scan (R14/R16-proven body): 2-term, register h_old, hoisted A-frag
// loads, gx double-buffered, scattered u16 h-publish, release-atomic barrier.
// Out-writes go directly into A-fragment layout for layer-1 GEMM.
// ---------------------------------------------------------------------------
__global__ __launch_bounds__(512) void gru_scan_hmma(
    const float* __restrict__ gx, const float* __restrict__ w_hh,
    const float* __restrict__ b_hh, uint8_t* __restrict__ aout, int writeOut)
{
    __shared__ float red[16*768];

    const int tid=threadIdx.x, warp=tid>>5, lane=tid&31, j0=blockIdx.x*8;
    const unsigned nCta=gridDim.x;
    const int grp=lane>>2, tig=lane&3;
    const int gkt = blockIdx.x>>1;     // column tile (16 neurons)
    const int qhi = blockIdx.x&1;      // which 8-neuron half of the tile

    uint32_t Bh[3][4][2], Bl[3][4][2];
#pragma unroll
    for(int nt=0; nt<3; nt++){
        const float* wr = w_hh + (size_t)(nt*HH + j0 + grp)*HH;
#pragma unroll
        for(int kt=0; kt<4; kt++){
            int k0 = warp*64 + kt*16 + tig*2;
            float f0=wr[k0], f1=wr[k0+1], f2=wr[k0+8], f3=wr[k0+9];
            __half h0,l0,h1,l1,h2,l2,h3,l3;
            split_h(f0,h0,l0); split_h(f1,h1,l1); split_h(f2,h2,l2); split_h(f3,h3,l3);
            Bh[nt][kt][0]=pack_h2(h0,h1); Bh[nt][kt][1]=pack_h2(h2,h3);
            Bl[nt][kt][0]=pack_h2(l0,l1); Bl[nt][kt][1]=pack_h2(l2,l3);
        }
    }

    const int gb=tid>>3, gnr=tid&7;
    float br_=0.f,bz_=0.f,bn_=0.f;
    size_t woff=0;
    float hold=0.f;
    float xr=0.f,xz=0.f,xn=0.f;
    if(tid<256){
        br_=b_hh[j0+gnr]; bz_=b_hh[HH+j0+gnr]; bn_=b_hh[2*HH+j0+gnr];
        int j=j0+gnr, jkt=j>>4, c=j&15, mt=gb>>4, r=gb&15;
        int ln=(r&7)*4+((c>>1)&3), q=((r>>3)&1)+2*((c>>3)&1);
        woff=(((size_t)(jkt*2+mt))<<9) + ln*16 + q*4 + (c&1)*2;
        size_t gbase=((size_t)gb*TT)*G3+(j0+gnr);
        xr=__ldg(&gx[gbase]); xz=__ldg(&gx[gbase+HH]); xn=__ldg(&gx[gbase+2*HH]);
    }

#pragma unroll 1
    for(int t=0; t<TT; t++){
        const uint8_t* pHiC=g_pHi[t&1];
        uint8_t* pHiN=g_pHi[(t+1)&1];

        if(writeOut && tid<256 && t>0){
            int tp=t-1;
            __half hv=__float2half_rn(hold);
            size_t tm=(size_t)gb*32 + (tp>>4);
            int lane_a=(tp&7)*4 + (gnr>>1);
            size_t ab=((tm*64 + gkt)*32 + lane_a)*16
                      + (size_t)qhi*8 + ((tp&8)>>3)*4 + (gnr&1)*2;
            st_u16_cg(aout + ab, *(unsigned short*)&hv);
        }

        uint4 Ah[2][4];
#pragma unroll
        for(int mt=0; mt<2; mt++)
#pragma unroll
            for(int kt=0; kt<4; kt++){
                int gkt2=warp*4+kt;
                size_t off=(((size_t)(gkt2*2+mt))<<9)+lane*16;
                Ah[mt][kt]=ld_u128_cg(pHiC+off);
            }

#pragma unroll
        for(int mt=0; mt<2; mt++){
            float C[3][4];
#pragma unroll
            for(int nt=0;nt<3;nt++)
#pragma unroll
                for(int i=0;i<4;i++) C[nt][i]=0.f;
#pragma unroll
            for(int nt=0; nt<3; nt++){
#pragma unroll
                for(int kt=0; kt<4; kt++){
                    mma16816(C[nt], (const uint32_t*)&Ah[mt][kt], Bh[nt][kt]);
                    mma16816(C[nt], (const uint32_t*)&Ah[mt][kt], Bl[nt][kt]);
                }
            }
#pragma unroll
            for(int nt=0; nt<3; nt++){
                float* rb=&red[warp*768 + (mt*3+nt)*128];
                int p0=grp*8+tig*2;
                rb[p0]=C[nt][0]; rb[p0+1]=C[nt][1];
                rb[p0+64]=C[nt][2]; rb[p0+65]=C[nt][3];
            }
        }
        __syncthreads();

        float xr2=0.f,xz2=0.f,xn2=0.f;
        if(tid<256){
            int mt=gb>>4, r=gb&15;
            float pr=0.f,pz=0.f,pn=0.f;
#pragma unroll
            for(int w=0; w<16; w++){
                int base=w*768 + mt*384 + r*8 + gnr;
                pr+=red[base];
                pz+=red[base+128];
                pn+=red[base+256];
            }
            float rr=1.f/(1.f+__expf(-(xr+pr+br_)));
            float zz=1.f/(1.f+__expf(-(xz+pz+bz_)));
            float nn=tanhf(xn+rr*(pn+bn_));
            float hnew=(1.f-zz)*nn+zz*hold;
            hold=hnew;
            __half hi=__float2half_rn(hnew);
            st_u16_cg(pHiN+woff, *(unsigned short*)&hi);
            if(t+1<TT){
                size_t gbase=((size_t)gb*TT+(t+1))*G3+(j0+gnr);
                xr2=__ldg(&gx[gbase]); xz2=__ldg(&gx[gbase+HH]); xn2=__ldg(&gx[gbase+2*HH]);
            }
        }

        __syncthreads();
        if(tid==0){
            atom_add_release(&g_bar, 1u);
            unsigned target=nCta*(unsigned)(t+1);
            while(ld_acquire_gpu(&g_bar) < target){}
        }
        __syncthreads();

        xr=xr2; xz=xz2; xn=xn2;
    }

    if(tid<256){
        if(writeOut){
            int tp=TT-1;
            __half hv=__float2half_rn(hold);
            size_t tm=(size_t)gb*32 + (tp>>4);
            int lane_a=(tp&7)*4 + (gnr>>1);
            size_t ab=((tm*64 + gkt)*32 + lane_a)*16
                      + (size_t)qhi*8 + ((tp&8)>>3)*4 + (gnr&1)*2;
            st_u16_cg(aout + ab, *(unsigned short*)&hv);
        }
        g_ha[gb*HH+j0+gnr]=hold;
    }
}

// ---- FC ----
__global__ __launch_bounds__(256) void fc_kernel(
    const float* __restrict__ h, const float* __restrict__ w,
    const float* __restrict__ bias, float* __restrict__ outp)
{
    int gw=(int)((blockIdx.x*blockDim.x+threadIdx.x)>>5), lane=threadIdx.x&31;
    if(gw>=BB*DOUT) return;
    int m=gw>>8, o=gw&255;
    float acc=0.f;
#pragma unroll
    for(int i=0;i<8;i++){
        float4 hv=*(const float4*)&h[m*HH+i*128+lane*4];
        float4 wv=*(const float4*)&w[o*HH+i*128+lane*4];
        acc+=hv.x*wv.x+hv.y*wv.y+hv.z*wv.z+hv.w*wv.w;
    }
#pragma unroll
    for(int off=16;off>0;off>>=1) acc+=__shfl_xor_sync(0xffffffffu,acc,off);
    if(lane==0) outp[m*DOUT+o]=1.f/(1.f+__expf(-(acc+bias[o])));
}

extern "C" void kernel_launch(void* const* d_in, const int* in_sizes, int n_in,
                              void* d_out, int out_size)
{
    const float* input=(const float*)d_in[0];
    const float* w_ih0=(const float*)d_in[1];
    const float* w_hh0=(const float*)d_in[2];
    const float* b_ih0=(const float*)d_in[3];
    const float* b_hh0=(const float*)d_in[4];
    const float* w_ih1=(const float*)d_in[5];
    const float* w_hh1=(const float*)d_in[6];
    const float* b_ih1=(const float*)d_in[7];
    const float* b_hh1=(const float*)d_in[8];
    const float* fc_w=(const float*)d_in[9];
    const float* fc_b=(const float*)d_in[10];
    float* outp=(float*)d_out;

    float *gx,*ha; unsigned* bar; uint8_t *pHi,*AhF,*BhF,*BlF;
    cudaGetSymbolAddress((void**)&gx,g_gx);
    cudaGetSymbolAddress((void**)&ha,g_ha);
    cudaGetSymbolAddress((void**)&bar,g_bar);
    cudaGetSymbolAddress((void**)&pHi,g_pHi);
    cudaGetSymbolAddress((void**)&AhF,g_AhF);
    cudaGetSymbolAddress((void**)&BhF,g_BhF);
    cudaGetSymbolAddress((void**)&BlF,g_BlF);

    dim3 ggrid(G3/128, MTOT/128);   // 24 x 128

    // ---- Layer 0 ----
    {
        int tA = (MTOT>>4)*(DIN>>4)*32;
        int tB = (G3>>3)*(DIN>>4)*32;
        splitA_frag<<<(tA+255)/256,256>>>(input, AhF, MTOT, DIN);
        splitB_frag<<<(tB+255)/256,256>>>(w_ih0, BhF, BlF, G3, DIN);
    }
    gemm_hmma_frag<<<ggrid,256>>>(AhF,BhF,BlF,b_ih0,gx,MTOT,G3,DIN);

    cudaMemsetAsync(pHi,0,BB*HH*2);            // h-frag buffer 0 = zeros
    cudaMemsetAsync(bar,0,sizeof(unsigned));
    // scan0 writes out0 directly into A-fragment layout (AhF already consumed)
    gru_scan_hmma<<<NCTA,512>>>(gx,w_hh0,b_hh0,AhF,1);
    cudaMemcpyAsync(outp+BB*DOUT,ha,BB*HH*sizeof(float),cudaMemcpyDeviceToDevice);

    // ---- Layer 1 (no splitA needed — AhF already in fragment form) ----
    {
        int tB = (G3>>3)*(HH>>4)*32;
        splitB_frag<<<(tB+255)/256,256>>>(w_ih1, BhF, BlF, G3, HH);
    }
    gemm_hmma_frag<<<ggrid,256>>>(AhF,BhF,BlF,b_ih1,gx,MTOT,G3,HH);

    cudaMemsetAsync(pHi,0,BB*HH*2);
    cudaMemsetAsync(bar,0,sizeof(unsigned));
    gru_scan_hmma<<<NCTA,512>>>(gx,w_hh1,b_hh1,nullptr,0);
    cudaMemcpyAsync(outp+BB*DOUT+BB*HH,ha,BB*HH*sizeof(float),cudaMemcpyDeviceToDevice);

    fc_kernel<<<(BB*DOUT*32)/256,256>>>(ha,fc_w,fc_b,outp);
}